// round 16
// baseline (speedup 1.0000x reference)
#include <cuda_runtime.h>
#include <cuda_fp16.h>
#include <cstdint>

#define D 64
#define M_MAX 1000000

// Scratch: y_all^T in fp16, m-major: g_yT[m*64 + d] = (W @ values)[d, m]. (128 MB)
__device__ __half g_yT[(size_t)M_MAX * D];

// ---------------- helpers ----------------
__device__ __forceinline__ uint32_t smem_u32(const void* p) {
    uint32_t a;
    asm("{ .reg .u64 t; cvta.to.shared.u64 t, %1; cvt.u32.u64 %0, t; }" : "=r"(a) : "l"(p));
    return a;
}

__device__ __forceinline__ uint32_t pack_f16x2(float lo_elem, float hi_elem) {
    __half2 h = __floats2half2_rn(lo_elem, hi_elem);   // .x = low 16 bits
    return *reinterpret_cast<uint32_t*>(&h);
}

// ldmatrix x4 (non-transposed), baseline PTX ISA.
__device__ __forceinline__ void ldsm4(uint32_t* r, uint32_t addr) {
    asm volatile("ldmatrix.sync.aligned.m8n8.x4.shared.b16 {%0,%1,%2,%3}, [%4];"
                 : "=r"(r[0]), "=r"(r[1]), "=r"(r[2]), "=r"(r[3]) : "r"(addr));
}

// mma.sync m16n8k16 row.col fp16 -> f32 accumulate.
__device__ __forceinline__ void mma16816(float* c, const uint32_t* a, const uint32_t* b) {
    asm volatile(
        "mma.sync.aligned.m16n8k16.row.col.f32.f16.f16.f32 "
        "{%0,%1,%2,%3}, {%4,%5,%6,%7}, {%8,%9}, {%0,%1,%2,%3};"
        : "+f"(c[0]), "+f"(c[1]), "+f"(c[2]), "+f"(c[3])
        : "r"(a[0]), "r"(a[1]), "r"(a[2]), "r"(a[3]), "r"(b[0]), "r"(b[1]));
}

// ---- cache-policy ops via createpolicy + .L2::cache_hint ----
__device__ __forceinline__ uint64_t mkpolicy_el() {
    uint64_t p;
    asm("createpolicy.fractional.L2::evict_last.b64 %0, 1.0;" : "=l"(p));
    return p;
}
__device__ __forceinline__ uint64_t mkpolicy_ef() {
    uint64_t p;
    asm("createpolicy.fractional.L2::evict_first.b64 %0, 1.0;" : "=l"(p));
    return p;
}
__device__ __forceinline__ float ldg_hint_f32(const float* p, uint64_t pol) {
    float v;
    asm volatile("ld.global.nc.L2::cache_hint.f32 %0, [%1], %2;" : "=f"(v) : "l"(p), "l"(pol));
    return v;
}
__device__ __forceinline__ void stg_hint_b32(void* p, uint32_t v, uint64_t pol) {
    asm volatile("st.global.L2::cache_hint.b32 [%0], %1, %2;" :: "l"(p), "r"(v), "l"(pol) : "memory");
}
__device__ __forceinline__ uint4 ldg_hint_v4(const uint4* p, uint64_t pol) {
    uint4 v;
    asm volatile("ld.global.nc.L2::cache_hint.v4.u32 {%0,%1,%2,%3}, [%4], %5;"
                 : "=r"(v.x), "=r"(v.y), "=r"(v.z), "=r"(v.w) : "l"(p), "l"(pol));
    return v;
}
__device__ __forceinline__ void stg_hint_v4(float* p, float4 v, uint64_t pol) {
    asm volatile("st.global.L2::cache_hint.v4.f32 [%0], {%1,%2,%3,%4}, %5;"
                 :: "l"(p), "f"(v.x), "f"(v.y), "f"(v.z), "f"(v.w), "l"(pol) : "memory");
}
__device__ __forceinline__ void stg_hint_f32(float* p, float v, uint64_t pol) {
    asm volatile("st.global.L2::cache_hint.f32 [%0], %1, %2;" :: "l"(p), "f"(v), "l"(pol) : "memory");
}

// Padded layout: row stride 144B (128B data + 16B pad) -> conflict-free
// STS.128 transpose stores; ldmatrix reads fine (16B-aligned per-lane addrs).
#define ROWSTRIDE 144
__device__ __forceinline__ uint32_t off144(int row, int k) {   // k in halfs (multiple of 8)
    return (uint32_t)(row * ROWSTRIDE + (k >> 3) * 16);
}

__device__ __forceinline__ void sts128(uint32_t addr, uint32_t r0, uint32_t r1, uint32_t r2, uint32_t r3) {
    asm volatile("st.shared.v4.b32 [%0], {%1,%2,%3,%4};"
                 :: "r"(addr), "r"(r0), "r"(r1), "r"(r2), "r"(r3) : "memory");
}

// Exact truncation split: hi = a with low 13 mantissa bits cleared (fits f16
// significand exactly; cvt is exact), lo = a - hi (exact). Residual ~2^-22.
__device__ __forceinline__ void split_f16(float a, float& ha, float& la) {
    ha = __uint_as_float(__float_as_uint(a) & 0xFFFFE000u);
    la = a - ha;
}

// ---------- K1: y_all^T = (W @ values)^T, 2-product fp16 split MMA ----------
__global__ __launch_bounds__(128)
void k1_tensor(const float* __restrict__ values, const float* __restrict__ weight, int M) {
    __shared__ __align__(16) char A_hi[128 * ROWSTRIDE];   // 18432 B
    __shared__ __align__(16) char A_lo[128 * ROWSTRIDE];   // 18432 B
    __shared__ __align__(16) char B_h[64 * ROWSTRIDE];     //  9216 B

    int t = threadIdx.x;
    int wid = t >> 5, lane = t & 31;
    uint32_t a_hi_b = smem_u32(A_hi), a_lo_b = smem_u32(A_lo), b_h_b = smem_u32(B_h);
    uint64_t pol_ef = mkpolicy_ef();
    uint64_t pol_el = mkpolicy_el();

    // --- Stage W -> B_h: thread t handles row d = t>>1, k-halfs [(t&1)*32, +32) ---
    {
        int d = t >> 1;
        int kh = (t & 1) * 32;
        const float* wrow = weight + d * 64 + kh;
        #pragma unroll
        for (int q = 0; q < 4; q++) {
            float4 wa = *(const float4*)(wrow + q * 8);
            float4 wb = *(const float4*)(wrow + q * 8 + 4);
            sts128(b_h_b + off144(d, kh + q * 8),
                   pack_f16x2(wa.x, wa.y), pack_f16x2(wa.z, wa.w),
                   pack_f16x2(wb.x, wb.y), pack_f16x2(wb.z, wb.w));
        }
    }

    // --- Stage + transpose values -> A_hi/A_lo: thread t owns column m = m0+t ---
    long long m0 = (long long)blockIdx.x * 128;
    {
        long long mg = m0 + t;
        const float* src = values + ((mg < (long long)M) ? mg : 0);
        float v[64];
        #pragma unroll
        for (int k = 0; k < 64; k++)
            v[k] = ldg_hint_f32(src + (size_t)k * M, pol_ef);
        #pragma unroll
        for (int kg = 0; kg < 8; kg++) {
            uint32_t hi[4], lo[4];
            #pragma unroll
            for (int j = 0; j < 4; j++) {
                float a = v[kg * 8 + 2 * j];
                float b = v[kg * 8 + 2 * j + 1];
                float ha, la, hb, lb;
                split_f16(a, ha, la);
                split_f16(b, hb, lb);
                hi[j] = pack_f16x2(ha, hb);
                lo[j] = pack_f16x2(la, lb);
            }
            sts128(a_hi_b + off144(t, kg * 8), hi[0], hi[1], hi[2], hi[3]);
            sts128(a_lo_b + off144(t, kg * 8), lo[0], lo[1], lo[2], lo[3]);
        }
    }
    __syncthreads();

    float acc[2][8][4];
    #pragma unroll
    for (int mt = 0; mt < 2; mt++)
        #pragma unroll
        for (int nt = 0; nt < 8; nt++)
            #pragma unroll
            for (int r = 0; r < 4; r++) acc[mt][nt][r] = 0.0f;

    int mbase = wid * 32;
    int a_row_l = lane & 15;
    int a_k_l   = (lane >> 4) * 8;
    int b_n_l = ((lane >> 4) << 3) + (lane & 7);
    int b_k_l = ((lane >> 3) & 1) * 8;

    #pragma unroll
    for (int ks = 0; ks < 4; ks++) {
        int k0 = ks * 16;
        uint32_t bfr[4][4];
        #pragma unroll
        for (int ntp = 0; ntp < 4; ntp++)
            ldsm4(bfr[ntp], b_h_b + off144(ntp * 16 + b_n_l, k0 + b_k_l));
        #pragma unroll
        for (int p = 0; p < 2; p++) {
            uint32_t Ab = p ? a_lo_b : a_hi_b;
            uint32_t afr[2][4];
            #pragma unroll
            for (int mt = 0; mt < 2; mt++)
                ldsm4(afr[mt], Ab + off144(mbase + mt * 16 + a_row_l, k0 + a_k_l));
            #pragma unroll
            for (int ntp = 0; ntp < 4; ntp++)
                #pragma unroll
                for (int mt = 0; mt < 2; mt++) {
                    mma16816(acc[mt][2 * ntp],     afr[mt], bfr[ntp]);
                    mma16816(acc[mt][2 * ntp + 1], afr[mt], bfr[ntp] + 2);
                }
        }
    }

    // --- Epilogue: fp32 acc -> fp16 scratch, evict_last (K2 reads it next) ---
    int g  = lane >> 2;
    int tg = lane & 3;
    #pragma unroll
    for (int mt = 0; mt < 2; mt++) {
        long long mA = m0 + mbase + mt * 16 + g;
        long long mB = mA + 8;
        #pragma unroll
        for (int nt = 0; nt < 8; nt++) {
            int d0 = nt * 8 + tg * 2;
            if (mA < (long long)M) {
                __half2 h = __floats2half2_rn(acc[mt][nt][0], acc[mt][nt][1]);
                stg_hint_b32(&g_yT[(size_t)mA * D + d0], *(uint32_t*)&h, pol_el);
            }
            if (mB < (long long)M) {
                __half2 h = __floats2half2_rn(acc[mt][nt][2], acc[mt][nt][3]);
                stg_hint_b32(&g_yT[(size_t)mB * D + d0], *(uint32_t*)&h, pol_el);
            }
        }
    }
}

// ---------- K2: out[:, j] = fp32(y_all^T[in_idx[out_idx[j]], :]) ----------
// JT=128 cols, 512 threads. Each thread privately chases out_idx -> in_idx
// (4 lanes/col load identical addresses -> broadcast; idx arrays are
// L2-resident at 8MB each) -> no cols[] smem, no first barrier.
#define JT 128
__global__ __launch_bounds__(512)
void k2_gather(const int* __restrict__ in_idx, const int* __restrict__ out_idx,
               float* __restrict__ out, int n_out) {
    __shared__ float ys[JT][D + 1];

    int t = threadIdx.x;
    long long j0 = (long long)blockIdx.x * JT;
    uint64_t pol_ef = mkpolicy_ef();
    uint64_t pol_el = mkpolicy_el();

    int col = t >> 2;   // 0..127
    int sub = t & 3;    // 0..3
    long long jj = j0 + col;
    long long c = 0;
    if (jj < n_out) {
        int oj = __ldg(out_idx + jj);
        c = __ldg(in_idx + oj);
    }

    const uint4* src = (const uint4*)&g_yT[(size_t)c * D];
#pragma unroll
    for (int i = 0; i < 2; i++) {
        int q = i * 4 + sub;             // uint4 index 0..7
        uint4 v = ldg_hint_v4(src + q, pol_el);
        float* dst = &ys[col][q * 8];
        float2 f;
        f = __half22float2(*(__half2*)&v.x); dst[0] = f.x; dst[1] = f.y;
        f = __half22float2(*(__half2*)&v.y); dst[2] = f.x; dst[3] = f.y;
        f = __half22float2(*(__half2*)&v.z); dst[4] = f.x; dst[5] = f.y;
        f = __half22float2(*(__half2*)&v.w); dst[6] = f.x; dst[7] = f.y;
    }
    __syncthreads();

    // Transposed write-out (STG.128 along j), evict_first (pure stream).
    // 64 d x 32 j-quads = 2048 tasks, 4 per thread; warp covers one d row,
    // 512B contiguous.
#pragma unroll
    for (int r = 0; r < 4; r++) {
        int flat = r * 512 + t;          // 0..2047
        int d  = flat >> 5;              // 0..63
        int jq = flat & 31;              // 0..31
        int jl = jq * 4;
        long long jw = j0 + jl;
        if (jw + 3 < n_out) {
            float4 v = make_float4(ys[jl][d], ys[jl + 1][d], ys[jl + 2][d], ys[jl + 3][d]);
            stg_hint_v4(&out[(size_t)d * n_out + jw], v, pol_ef);
        } else {
            for (int u = 0; u < 4 && jw + u < n_out; u++)
                stg_hint_f32(&out[(size_t)d * n_out + jw + u], ys[jl + u][d], pol_ef);
        }
    }
}

extern "C" void kernel_launch(void* const* d_in, const int* in_sizes, int n_in,
                              void* d_out, int out_size) {
    const float* values  = (const float*)d_in[0];   // (64, M) row-major
    const float* weight  = (const float*)d_in[1];   // (64, 64) row-major
    const int*   in_idx  = (const int*)d_in[2];     // (N_IN,)
    const int*   out_idx = (const int*)d_in[3];     // (N_OUT,)
    float*       out     = (float*)d_out;           // (64, N_OUT) row-major

    int M     = in_sizes[0] / D;
    int n_out = in_sizes[3];

    int g1 = (M + 127) / 128;
    k1_tensor<<<g1, 128>>>(values, weight, M);

    int g2 = (n_out + JT - 1) / JT;
    k2_gather<<<g2, 512>>>(in_idx, out_idx, out, n_out);
}

// round 17
// speedup vs baseline: 1.1123x; 1.1123x over previous
#include <cuda_runtime.h>
#include <cuda_fp16.h>
#include <cstdint>

#define D 64
#define M_MAX 1000000

// Scratch: y_all^T in fp16, m-major: g_yT[m*64 + d] = (W @ values)[d, m]. (128 MB)
__device__ __half g_yT[(size_t)M_MAX * D];

// ---------------- helpers ----------------
__device__ __forceinline__ uint32_t smem_u32(const void* p) {
    uint32_t a;
    asm("{ .reg .u64 t; cvta.to.shared.u64 t, %1; cvt.u32.u64 %0, t; }" : "=r"(a) : "l"(p));
    return a;
}

__device__ __forceinline__ uint32_t pack_f16x2(float lo_elem, float hi_elem) {
    __half2 h = __floats2half2_rn(lo_elem, hi_elem);   // .x = low 16 bits
    return *reinterpret_cast<uint32_t*>(&h);
}

// ldmatrix x4 (non-transposed), baseline PTX ISA.
__device__ __forceinline__ void ldsm4(uint32_t* r, uint32_t addr) {
    asm volatile("ldmatrix.sync.aligned.m8n8.x4.shared.b16 {%0,%1,%2,%3}, [%4];"
                 : "=r"(r[0]), "=r"(r[1]), "=r"(r[2]), "=r"(r[3]) : "r"(addr));
}

// mma.sync m16n8k16 row.col fp16 -> f32 accumulate.
__device__ __forceinline__ void mma16816(float* c, const uint32_t* a, const uint32_t* b) {
    asm volatile(
        "mma.sync.aligned.m16n8k16.row.col.f32.f16.f16.f32 "
        "{%0,%1,%2,%3}, {%4,%5,%6,%7}, {%8,%9}, {%0,%1,%2,%3};"
        : "+f"(c[0]), "+f"(c[1]), "+f"(c[2]), "+f"(c[3])
        : "r"(a[0]), "r"(a[1]), "r"(a[2]), "r"(a[3]), "r"(b[0]), "r"(b[1]));
}

// ---- cache-policy ops via createpolicy + .L2::cache_hint ----
__device__ __forceinline__ uint64_t mkpolicy_el() {
    uint64_t p;
    asm("createpolicy.fractional.L2::evict_last.b64 %0, 1.0;" : "=l"(p));
    return p;
}
__device__ __forceinline__ uint64_t mkpolicy_ef() {
    uint64_t p;
    asm("createpolicy.fractional.L2::evict_first.b64 %0, 1.0;" : "=l"(p));
    return p;
}
__device__ __forceinline__ float ldg_hint_f32(const float* p, uint64_t pol) {
    float v;
    asm volatile("ld.global.nc.L2::cache_hint.f32 %0, [%1], %2;" : "=f"(v) : "l"(p), "l"(pol));
    return v;
}
__device__ __forceinline__ void stg_hint_b32(void* p, uint32_t v, uint64_t pol) {
    asm volatile("st.global.L2::cache_hint.b32 [%0], %1, %2;" :: "l"(p), "r"(v), "l"(pol) : "memory");
}
__device__ __forceinline__ uint4 ldg_hint_v4(const uint4* p, uint64_t pol) {
    uint4 v;
    asm volatile("ld.global.nc.L2::cache_hint.v4.u32 {%0,%1,%2,%3}, [%4], %5;"
                 : "=r"(v.x), "=r"(v.y), "=r"(v.z), "=r"(v.w) : "l"(p), "l"(pol));
    return v;
}
__device__ __forceinline__ void stg_hint_v4(float* p, float4 v, uint64_t pol) {
    asm volatile("st.global.L2::cache_hint.v4.f32 [%0], {%1,%2,%3,%4}, %5;"
                 :: "l"(p), "f"(v.x), "f"(v.y), "f"(v.z), "f"(v.w), "l"(pol) : "memory");
}
__device__ __forceinline__ void stg_hint_f32(float* p, float v, uint64_t pol) {
    asm volatile("st.global.L2::cache_hint.f32 [%0], %1, %2;" :: "l"(p), "f"(v), "l"(pol) : "memory");
}

// Padded layout: row stride 144B (128B data + 16B pad) -> conflict-free
// STS.128 transpose stores; ldmatrix reads fine (16B-aligned per-lane addrs).
#define ROWSTRIDE 144
__device__ __forceinline__ uint32_t off144(int row, int k) {   // k in halfs (multiple of 8)
    return (uint32_t)(row * ROWSTRIDE + (k >> 3) * 16);
}

__device__ __forceinline__ void sts128(uint32_t addr, uint32_t r0, uint32_t r1, uint32_t r2, uint32_t r3) {
    asm volatile("st.shared.v4.b32 [%0], {%1,%2,%3,%4};"
                 :: "r"(addr), "r"(r0), "r"(r1), "r"(r2), "r"(r3) : "memory");
}

// ---------- K1: y_all^T = (W @ values)^T, single-product fp16 MMA ----------
// Both A (values^T tile) and B (W) in single fp16: independent roundings,
// aggregate y rel-err ~4.2e-4 incl. fp16 scratch -- under the 1e-3 threshold.
// Halves MMA count, A-staging STS, and conversion ALU vs the 2-product split.
__global__ __launch_bounds__(128)
void k1_tensor(const float* __restrict__ values, const float* __restrict__ weight, int M) {
    __shared__ __align__(16) char A_h[128 * ROWSTRIDE];    // 18432 B
    __shared__ __align__(16) char B_h[64 * ROWSTRIDE];     //  9216 B

    int t = threadIdx.x;
    int wid = t >> 5, lane = t & 31;
    uint32_t a_h_b = smem_u32(A_h), b_h_b = smem_u32(B_h);
    uint64_t pol_ef = mkpolicy_ef();
    uint64_t pol_el = mkpolicy_el();

    // --- Stage W -> B_h: thread t handles row d = t>>1, k-halfs [(t&1)*32, +32) ---
    {
        int d = t >> 1;
        int kh = (t & 1) * 32;
        const float* wrow = weight + d * 64 + kh;
        #pragma unroll
        for (int q = 0; q < 4; q++) {
            float4 wa = *(const float4*)(wrow + q * 8);
            float4 wb = *(const float4*)(wrow + q * 8 + 4);
            sts128(b_h_b + off144(d, kh + q * 8),
                   pack_f16x2(wa.x, wa.y), pack_f16x2(wa.z, wa.w),
                   pack_f16x2(wb.x, wb.y), pack_f16x2(wb.z, wb.w));
        }
    }

    // --- Stage + transpose values -> A_h: thread t owns column m = m0+t ---
    long long m0 = (long long)blockIdx.x * 128;
    {
        long long mg = m0 + t;
        const float* src = values + ((mg < (long long)M) ? mg : 0);
        float v[64];
        #pragma unroll
        for (int k = 0; k < 64; k++)
            v[k] = ldg_hint_f32(src + (size_t)k * M, pol_ef);
        #pragma unroll
        for (int kg = 0; kg < 8; kg++) {
            uint32_t hi[4];
            #pragma unroll
            for (int j = 0; j < 4; j++)
                hi[j] = pack_f16x2(v[kg * 8 + 2 * j], v[kg * 8 + 2 * j + 1]);
            sts128(a_h_b + off144(t, kg * 8), hi[0], hi[1], hi[2], hi[3]);
        }
    }
    __syncthreads();

    float acc[2][8][4];
    #pragma unroll
    for (int mt = 0; mt < 2; mt++)
        #pragma unroll
        for (int nt = 0; nt < 8; nt++)
            #pragma unroll
            for (int r = 0; r < 4; r++) acc[mt][nt][r] = 0.0f;

    int mbase = wid * 32;
    int a_row_l = lane & 15;
    int a_k_l   = (lane >> 4) * 8;
    int b_n_l = ((lane >> 4) << 3) + (lane & 7);
    int b_k_l = ((lane >> 3) & 1) * 8;

    #pragma unroll
    for (int ks = 0; ks < 4; ks++) {
        int k0 = ks * 16;
        uint32_t bfr[4][4];
        #pragma unroll
        for (int ntp = 0; ntp < 4; ntp++)
            ldsm4(bfr[ntp], b_h_b + off144(ntp * 16 + b_n_l, k0 + b_k_l));
        uint32_t afr[2][4];
        #pragma unroll
        for (int mt = 0; mt < 2; mt++)
            ldsm4(afr[mt], a_h_b + off144(mbase + mt * 16 + a_row_l, k0 + a_k_l));
        #pragma unroll
        for (int ntp = 0; ntp < 4; ntp++)
            #pragma unroll
            for (int mt = 0; mt < 2; mt++) {
                mma16816(acc[mt][2 * ntp],     afr[mt], bfr[ntp]);
                mma16816(acc[mt][2 * ntp + 1], afr[mt], bfr[ntp] + 2);
            }
    }

    // --- Epilogue: fp32 acc -> fp16 scratch, evict_last (K2 reads it next) ---
    int g  = lane >> 2;
    int tg = lane & 3;
    #pragma unroll
    for (int mt = 0; mt < 2; mt++) {
        long long mA = m0 + mbase + mt * 16 + g;
        long long mB = mA + 8;
        #pragma unroll
        for (int nt = 0; nt < 8; nt++) {
            int d0 = nt * 8 + tg * 2;
            if (mA < (long long)M) {
                __half2 h = __floats2half2_rn(acc[mt][nt][0], acc[mt][nt][1]);
                stg_hint_b32(&g_yT[(size_t)mA * D + d0], *(uint32_t*)&h, pol_el);
            }
            if (mB < (long long)M) {
                __half2 h = __floats2half2_rn(acc[mt][nt][2], acc[mt][nt][3]);
                stg_hint_b32(&g_yT[(size_t)mB * D + d0], *(uint32_t*)&h, pol_el);
            }
        }
    }
}

// ---------- K2: out[:, j] = fp32(y_all^T[in_idx[out_idx[j]], :]) ----------
// (R15-winning shape: JT=64, 256 threads, cols[] smem index chase.)
#define JT 64
__global__ __launch_bounds__(256)
void k2_gather(const int* __restrict__ in_idx, const int* __restrict__ out_idx,
               float* __restrict__ out, int n_out) {
    __shared__ float ys[JT][D + 1];
    __shared__ int cols[JT];

    int t = threadIdx.x;
    int j0 = blockIdx.x * JT;
    uint64_t pol_ef = mkpolicy_ef();
    uint64_t pol_el = mkpolicy_el();

    if (t < JT) {
        int jj = j0 + t;
        int c = 0;
        if (jj < n_out) {
            int oj = out_idx[jj];
            c = in_idx[oj];
        }
        cols[t] = c;
    }
    __syncthreads();

    // Gather: 4 threads/col, evict_last (rows reused ~2.8x)
    int col = t >> 2;   // 0..63
    int sub = t & 3;    // 0..3
    long long c = cols[col];
    const uint4* src = (const uint4*)&g_yT[(size_t)c * D];
#pragma unroll
    for (int i = 0; i < 2; i++) {
        int q = i * 4 + sub;             // uint4 index 0..7
        uint4 v = ldg_hint_v4(src + q, pol_el);
        float* dst = &ys[col][q * 8];
        float2 f;
        f = __half22float2(*(__half2*)&v.x); dst[0] = f.x; dst[1] = f.y;
        f = __half22float2(*(__half2*)&v.y); dst[2] = f.x; dst[3] = f.y;
        f = __half22float2(*(__half2*)&v.z); dst[4] = f.x; dst[5] = f.y;
        f = __half22float2(*(__half2*)&v.w); dst[6] = f.x; dst[7] = f.y;
    }
    __syncthreads();

    // Vectorized transposed write-out (STG.128 along j), evict_first (pure stream).
#pragma unroll
    for (int r = 0; r < 4; r++) {
        int flat = r * 256 + t;          // 0..1023
        int d  = flat >> 4;              // 0..63
        int jq = flat & 15;              // 0..15
        int jl = jq * 4;
        long long jj = (long long)j0 + jl;
        if (jj + 3 < n_out) {
            float4 v = make_float4(ys[jl][d], ys[jl + 1][d], ys[jl + 2][d], ys[jl + 3][d]);
            stg_hint_v4(&out[(size_t)d * n_out + jj], v, pol_ef);
        } else {
            for (int u = 0; u < 4 && jj + u < n_out; u++)
                stg_hint_f32(&out[(size_t)d * n_out + jj + u], ys[jl + u][d], pol_ef);
        }
    }
}

extern "C" void kernel_launch(void* const* d_in, const int* in_sizes, int n_in,
                              void* d_out, int out_size) {
    const float* values  = (const float*)d_in[0];   // (64, M) row-major
    const float* weight  = (const float*)d_in[1];   // (64, 64) row-major
    const int*   in_idx  = (const int*)d_in[2];     // (N_IN,)
    const int*   out_idx = (const int*)d_in[3];     // (N_OUT,)
    float*       out     = (float*)d_out;           // (64, N_OUT) row-major

    int M     = in_sizes[0] / D;
    int n_out = in_sizes[3];

    int g1 = (M + 127) / 128;
    k1_tensor<<<g1, 128>>>(values, weight, M);

    int g2 = (n_out + JT - 1) / JT;
    k2_gather<<<g2, 256>>>(in_idx, out_idx, out, n_out);
}